// round 7
// baseline (speedup 1.0000x reference)
#include <cuda_runtime.h>
#include <math.h>

// Problem constants
#define BQ 4
#define NQ 23
#define NPAIR 15
#define RLQ 32
#define FEAT 1121          // 1 + 5*32 + 15*64
#define NW 23              // one warp per j-atom
#define NT (NW * 32)       // 736 threads

// 0.5*cos(theta_l), 0.5*sin(theta_l), theta_l = pi*l/7
__constant__ float CTH2[8] = {
     0.5f,            0.45048443395f,  0.31174490093f,  0.11126046698f,
    -0.11126046698f, -0.31174490093f, -0.45048443395f, -0.5f };
__constant__ float STH2[8] = {
     0.0f,            0.21694186956f,  0.39091574124f,  0.48746395609f,
     0.48746395609f,  0.39091574124f,  0.21694186956f,  0.0f };
// pair p -> (ta, tb), ta<=tb
__constant__ int PA[NPAIR] = {0,0,0,0,0,1,1,1,1,2,2,2,3,3,4};
__constant__ int PB[NPAIR] = {0,1,2,3,4,1,2,3,4,2,3,4,3,4,4};

__global__ __launch_bounds__(NT, 1)
void ani_kernel(const float* __restrict__ coords,
                const int*   __restrict__ anum,
                float*       __restrict__ out)
{
    __shared__ float4   rel[NQ];            // (dx,dy,dz,dist) wrt atom i
    __shared__ float    fac[NQ], frc[NQ];
    __shared__ int      typ[NQ];
    __shared__ unsigned amask[5];           // atoms with typ==t && fac>0
    __shared__ unsigned rmask[5];           // atoms with typ==t
    __shared__ float    wacc[NW][5 * 64];   // per-warp angular partials (29440 B)
    __shared__ float    radp[NW][RLQ];      // per-warp radial partials  (2944 B)

    const int bi = blockIdx.x;
    const int b  = bi / NQ;
    const int i  = bi % NQ;
    const int tid  = threadIdx.x;
    const int w    = tid >> 5;
    const int lane = tid & 31;

    // ---- warp 0 prepares all per-atom data ----
    if (w == 0) {
        const bool v = lane < NQ;
        float x = 0.f, y = 0.f, z = 0.f;
        int   t = -1;
        if (v) {
            const float BOHR = 0.52917721092f;
            x = coords[(b * NQ + lane) * 3 + 0] * BOHR;
            y = coords[(b * NQ + lane) * 3 + 1] * BOHR;
            z = coords[(b * NQ + lane) * 3 + 2] * BOHR;
            int zz = anum[b * NQ + lane];
            t = (zz == 1) ? 0 : (zz == 6) ? 1 : (zz == 7) ? 2 :
                (zz == 8) ? 3 : (zz == 16) ? 4 : -1;
        }
        const float xi = __shfl_sync(0xFFFFFFFFu, x, i);
        const float yi = __shfl_sync(0xFFFFFFFFu, y, i);
        const float zi = __shfl_sync(0xFFFFFFFFu, z, i);

        float dx = x - xi, dy = y - yi, dz = z - zi;
        float dr = sqrtf(dx * dx + dy * dy + dz * dz + 1e-7f);
        bool  ne = v && (lane != i);
        float fr = (ne && dr < 4.6f) ? 0.5f * (__cosf(0.68294733639181f * dr) + 1.0f) : 0.0f;
        float fa = (ne && dr < 3.1f) ? 0.5f * (__cosf(1.01341709287626f * dr) + 1.0f) : 0.0f;
        if (v) {
            rel[lane] = make_float4(dx, dy, dz, dr);
            frc[lane] = fr;
            fac[lane] = fa;
            typ[lane] = t;
        }
        #pragma unroll
        for (int tt = 0; tt < 5; tt++) {
            unsigned am = __ballot_sync(0xFFFFFFFFu, (t == tt) && (fa > 0.0f));
            unsigned rm = __ballot_sync(0xFFFFFFFFu, (t == tt));
            if (lane == 0) { amask[tt] = am; rmask[tt] = rm; }
        }
    }
    __syncthreads();

    const int   tj = typ[w];
    const float fj = fac[w];
    const float fw = frc[w];
    const float4 rj = rel[w];

    // ---- radial partial: warp w, one shell per lane ----
    {
        const float step = 4.6f / 31.0f;
        const float nita = -3.0f / (step * step);
        float rv = 0.0f;
        if (tj >= 0 && fw > 0.0f) {
            float dd = rj.w - step * (float)lane;
            rv = __expf(nita * dd * dd) * fw;
        }
        radp[w][lane] = rv;
    }

    // ---- angular: register accumulators, k grouped by type ----
    float acc[10] = {0.f,0.f,0.f,0.f,0.f,0.f,0.f,0.f,0.f,0.f};
    if (tj >= 0 && fj > 0.0f) {
        const float fj2 = 2.0f * fj;
        const float djh = 0.5f * rj.w;

        const int   thi  = lane & 7;
        const int   rsi  = lane >> 3;
        const float cth2 = CTH2[thi];
        const float sth2 = STH2[thi];
        const float ASTEP = 3.1f / 7.0f;
        const float rsa0  = ASTEP * (float)rsi;
        const float rsa1  = ASTEP * (float)(rsi + 4);
        const float NITA  = -3.0f / (ASTEP * ASTEP);

        #pragma unroll
        for (int s = 0; s < 5; s++) {
            const int t = tj + s;
            if (t <= 4) {
                unsigned m = amask[t];
                while (m) {
                    const int kk = __ffs(m) - 1; m &= m - 1;
                    const float4 rk = rel[kk];
                    const float  fk = fac[kk];

                    float vm = rj.x * rk.x + rj.y * rk.y + rj.z * rk.z;
                    float ct = __fdividef(vm, fmaf(rj.w, rk.w, 1e-5f));
                    float x2 = fmaxf(1.0f - ct * ct, 0.0f);
                    float st = x2 * rsqrtf(fmaxf(x2, 1e-12f));   // sin(arccos(ct))

                    // ((1 + cos(theta - th_l))/2)^64 via identity + 6 squarings
                    float a = fmaf(ct, cth2, fmaf(st, sth2, 0.5f));
                    a = a * a; a = a * a; a = a * a;
                    a = a * a; a = a * a; a = a * a;

                    float ravg = fmaf(rk.w, 0.5f, djh);
                    float d0 = ravg - rsa0;
                    float d1 = ravg - rsa1;
                    float g0 = __expf(NITA * d0 * d0);
                    float g1 = __expf(NITA * d1 * d1);

                    float sv = a * (fj2 * fk);
                    acc[2 * s]     += sv * g0;
                    acc[2 * s + 1] += sv * g1;
                }
            }
        }
    }

    // store per-warp partials (registers are zero for inactive warps)
    #pragma unroll
    for (int s = 0; s < 5; s++) {
        wacc[w][s * 64 + lane]      = acc[2 * s];
        wacc[w][s * 64 + 32 + lane] = acc[2 * s + 1];
    }
    __syncthreads();

    // ---- epilogue: reduce partials, write output ----
    const size_t base = (size_t)(b * NQ + i) * FEAT;
    if (tid == 0) out[base] = (float)anum[b * NQ + i];

    // radial: 160 outputs
    if (tid < 5 * RLQ) {
        const int t = tid >> 5, c = tid & 31;
        unsigned m = rmask[t];
        float s = 0.0f;
        while (m) { const int a = __ffs(m) - 1; m &= m - 1; s += radp[a][c]; }
        out[base + 1 + tid] = s;
    }

    // angular: 960 outputs
    for (int f = tid; f < NPAIR * 64; f += NT) {
        const int p = f >> 6, c = f & 63;
        const int ta = PA[p], tb = PB[p];
        const int slot = (tb - ta) * 64 + c;
        unsigned m = amask[ta];
        float s = 0.0f;
        while (m) { const int a = __ffs(m) - 1; m &= m - 1; s += wacc[a][slot]; }
        out[base + 1 + 5 * RLQ + f] = s;
    }
}

extern "C" void kernel_launch(void* const* d_in, const int* in_sizes, int n_in,
                              void* d_out, int out_size)
{
    const float* coords = (const float*)d_in[0];
    const int*   anum   = (const int*)d_in[1];
    float*       out    = (float*)d_out;
    ani_kernel<<<BQ * NQ, NT>>>(coords, anum, out);
}

// round 8
// speedup vs baseline: 1.0370x; 1.0370x over previous
#include <cuda_runtime.h>
#include <math.h>

// Problem constants
#define BQ 4
#define NQ 23
#define NPAIR 15
#define RLQ 32
#define FEAT 1121          // 1 + 5*32 + 15*64
#define NW 23              // one warp per j-atom
#define NT (NW * 32)       // 736 threads

// 0.5*cos(theta_l), 0.5*sin(theta_l), theta_l = pi*l/7
__constant__ float CTH2[8] = {
     0.5f,            0.45048443395f,  0.31174490093f,  0.11126046698f,
    -0.11126046698f, -0.31174490093f, -0.45048443395f, -0.5f };
__constant__ float STH2[8] = {
     0.0f,            0.21694186956f,  0.39091574124f,  0.48746395609f,
     0.48746395609f,  0.39091574124f,  0.21694186956f,  0.0f };
// pair p -> (ta, tb), ta<=tb
__constant__ int PA[NPAIR] = {0,0,0,0,0,1,1,1,1,2,2,2,3,3,4};
__constant__ int PB[NPAIR] = {0,1,2,3,4,1,2,3,4,2,3,4,3,4,4};

__global__ __launch_bounds__(NT, 1)
void ani_kernel(const float* __restrict__ coords,
                const int*   __restrict__ anum,
                float*       __restrict__ out)
{
    __shared__ float    wacc[NW][5 * 64];   // per-warp angular partials
    __shared__ float    radp[NW][RLQ];      // per-warp radial partials
    __shared__ unsigned s_amask[5];         // typ==t && fac>0 (for epilogue)
    __shared__ unsigned s_rmask[5];         // typ==t

    const int bi = blockIdx.x;
    const int b  = bi / NQ;
    const int i  = bi % NQ;
    const int tid  = threadIdx.x;
    const int w    = tid >> 5;
    const int lane = tid & 31;
    const unsigned FULL = 0xFFFFFFFFu;

    // ---- per-warp redundant prologue (no block sync, no warp-0 serial) ----
    const bool v = lane < NQ;
    float x = 0.f, y = 0.f, z = 0.f;
    int   t = -1;
    if (v) {
        const float BOHR = 0.52917721092f;
        x = coords[(b * NQ + lane) * 3 + 0] * BOHR;
        y = coords[(b * NQ + lane) * 3 + 1] * BOHR;
        z = coords[(b * NQ + lane) * 3 + 2] * BOHR;
        int zz = anum[b * NQ + lane];
        t = (zz == 1) ? 0 : (zz == 6) ? 1 : (zz == 7) ? 2 :
            (zz == 8) ? 3 : (zz == 16) ? 4 : -1;
    }
    const float xi = __shfl_sync(FULL, x, i);
    const float yi = __shfl_sync(FULL, y, i);
    const float zi = __shfl_sync(FULL, z, i);

    const float dx = x - xi, dy = y - yi, dz = z - zi;
    const float dr = sqrtf(dx * dx + dy * dy + dz * dz + 1e-7f);
    const bool  ne = v && (lane != i);
    const float fr = (ne && dr < 4.6f) ? 0.5f * (__cosf(0.68294733639181f * dr) + 1.0f) : 0.0f;
    const float fa = (ne && dr < 3.1f) ? 0.5f * (__cosf(1.01341709287626f * dr) + 1.0f) : 0.0f;

    unsigned am[5], rm[5];
    #pragma unroll
    for (int tt = 0; tt < 5; tt++) {
        am[tt] = __ballot_sync(FULL, (t == tt) && (fa > 0.0f));
        rm[tt] = __ballot_sync(FULL, (t == tt));
    }
    if (tid == 0) {
        #pragma unroll
        for (int tt = 0; tt < 5; tt++) { s_amask[tt] = am[tt]; s_rmask[tt] = rm[tt]; }
    }

    // j = w per-warp broadcast values
    const int   tj  = __shfl_sync(FULL, t,  w);
    const float fj  = __shfl_sync(FULL, fa, w);
    const float fjr = __shfl_sync(FULL, fr, w);
    const float djx = __shfl_sync(FULL, dx, w);
    const float djy = __shfl_sync(FULL, dy, w);
    const float djz = __shfl_sync(FULL, dz, w);
    const float djd = __shfl_sync(FULL, dr, w);

    // ---- radial partial: warp w, one shell per lane ----
    {
        const float step = 4.6f / 31.0f;
        const float nita = -3.0f / (step * step);
        float rv = 0.0f;
        if (tj >= 0 && fjr > 0.0f) {
            float dd = djd - step * (float)lane;
            rv = __expf(nita * dd * dd) * fjr;
        }
        radp[w][lane] = rv;
    }

    // ---- phase A: lane k computes per-pair (j=w, k=lane) scalars, once ----
    float ctP, stP, rvP, fpP;
    {
        float vm = djx * dx + djy * dy + djz * dz;
        float ct = __fdividef(vm, fmaf(djd, dr, 1e-5f));
        float x2 = fmaxf(1.0f - ct * ct, 0.0f);
        ctP = ct;
        stP = x2 * rsqrtf(fmaxf(x2, 1e-12f));   // sin(arccos(ct))
        rvP = fmaf(dr, 0.5f, 0.5f * djd);       // (d_j + d_k)/2
        fpP = 2.0f * fj * fa;                   // 2 f_j f_k
    }

    // ---- phase B: accumulate features, k grouped by type (warp-uniform) ----
    float acc[10] = {0.f,0.f,0.f,0.f,0.f,0.f,0.f,0.f,0.f,0.f};
    if (tj >= 0 && fj > 0.0f) {
        const int   thi  = lane & 7;
        const int   rsi  = lane >> 3;
        const float cth2 = CTH2[thi];
        const float sth2 = STH2[thi];
        const float ASTEP = 3.1f / 7.0f;
        const float myrsa = ASTEP * (float)thi;      // this lane's gaussian center
        const float NITA  = -3.0f / (ASTEP * ASTEP);

        #pragma unroll
        for (int s = 0; s < 5; s++) {
            const int tt = tj + s;
            if (tt <= 4) {
                unsigned m = am[tt];
                while (m) {
                    const int kk = __ffs(m) - 1; m &= m - 1;
                    const float ctk = __shfl_sync(FULL, ctP, kk);
                    const float stk = __shfl_sync(FULL, stP, kk);
                    const float rvk = __shfl_sync(FULL, rvP, kk);
                    const float fpk = __shfl_sync(FULL, fpP, kk);

                    // ((1 + cos(theta - th_l))/2)^64 via identity + 6 squarings
                    float a = fmaf(ctk, cth2, fmaf(stk, sth2, 0.5f));
                    a = a * a; a = a * a; a = a * a;
                    a = a * a; a = a * a; a = a * a;

                    // one gaussian per lane (index lane&7), broadcast to users
                    float dd = rvk - myrsa;
                    float gl = __expf(NITA * dd * dd);
                    float g0 = __shfl_sync(FULL, gl, rsi);
                    float g1 = __shfl_sync(FULL, gl, rsi + 4);

                    float sv = a * fpk;
                    acc[2 * s]     = fmaf(sv, g0, acc[2 * s]);
                    acc[2 * s + 1] = fmaf(sv, g1, acc[2 * s + 1]);
                }
            }
        }
    }

    // store per-warp partials (zeros for inactive warps)
    #pragma unroll
    for (int s = 0; s < 5; s++) {
        wacc[w][s * 64 + lane]      = acc[2 * s];
        wacc[w][s * 64 + 32 + lane] = acc[2 * s + 1];
    }
    __syncthreads();

    // ---- epilogue: reduce partials, write output ----
    const size_t base = (size_t)(b * NQ + i) * FEAT;
    if (tid == 0) out[base] = (float)anum[b * NQ + i];

    // radial: 160 outputs
    if (tid < 5 * RLQ) {
        const int tt = tid >> 5, c = tid & 31;
        unsigned m = s_rmask[tt];
        float s = 0.0f;
        while (m) { const int a = __ffs(m) - 1; m &= m - 1; s += radp[a][c]; }
        out[base + 1 + tid] = s;
    }

    // angular: 960 outputs
    for (int f = tid; f < NPAIR * 64; f += NT) {
        const int p = f >> 6, c = f & 63;
        const int ta = PA[p], tb = PB[p];
        const int slot = (tb - ta) * 64 + c;
        unsigned m = s_amask[ta];
        float s = 0.0f;
        while (m) { const int a = __ffs(m) - 1; m &= m - 1; s += wacc[a][slot]; }
        out[base + 1 + 5 * RLQ + f] = s;
    }
}

extern "C" void kernel_launch(void* const* d_in, const int* in_sizes, int n_in,
                              void* d_out, int out_size)
{
    const float* coords = (const float*)d_in[0];
    const int*   anum   = (const int*)d_in[1];
    float*       out    = (float*)d_out;
    ani_kernel<<<BQ * NQ, NT>>>(coords, anum, out);
}